// round 11
// baseline (speedup 1.0000x reference)
#include <cuda_runtime.h>
#include <cuda_fp16.h>
#include <cstdint>

// GCN layer: out = segment_mean( (h @ W^T)[src], dst )
//   h [100000,256] f32, W [128,256] f32, src/dst [1.6M] idx (dtype runtime-detected)
// fp16 single-pass HMMA GEMM (f32 accum) + fp16 z; CSR build overlapped with GEMM.

#define IN_F  256
#define OUT_F 128
#define MAX_NODES 100000
#define MAX_EDGES 1600000
#define SCAN_BLK  1024

__device__ __half   g_z16[(size_t)MAX_NODES * OUT_F];
__device__ int      g_count[MAX_NODES];
__device__ int      g_off[MAX_NODES];
__device__ int      g_cur[MAX_NODES];
__device__ int      g_srcs[MAX_EDGES];
__device__ int      g_blksum[(MAX_NODES + SCAN_BLK - 1) / SCAN_BLK + 1];
__device__ int      g_idx_is64;
__device__ unsigned g_Wh[OUT_F * IN_F / 2];   // W fp16 plane (packed f16x2)

static cudaStream_t g_s2;
static cudaEvent_t  g_evFork, g_evJoin;
static struct _StreamInit {
    _StreamInit() {
        cudaStreamCreateWithFlags(&g_s2, cudaStreamNonBlocking);
        cudaEventCreateWithFlags(&g_evFork, cudaEventDisableTiming);
        cudaEventCreateWithFlags(&g_evJoin, cudaEventDisableTiming);
    }
} g_streamInit;

// ---------------------------------------------------------------------------
__device__ __forceinline__ uint2 cvt4_f16(float4 v) {
    unsigned xy, zw;
    asm("cvt.rn.f16x2.f32 %0, %1, %2;" : "=r"(xy) : "f"(v.y), "f"(v.x));
    asm("cvt.rn.f16x2.f32 %0, %1, %2;" : "=r"(zw) : "f"(v.w), "f"(v.z));
    return make_uint2(xy, zw);
}

__global__ __launch_bounds__(256)
void prep_kernel(const unsigned long long* __restrict__ s64, int E,
                 const float* __restrict__ W, int M) {
    int i = blockIdx.x * blockDim.x + threadIdx.x;
    if (i == 0) {
        int n = E < 16 ? E : 16;
        int is64 = 1;
        for (int j = 0; j < n; j++)
            if ((s64[j] >> 32) != 0ull) { is64 = 0; break; }
        g_idx_is64 = is64;
    }
    if (i < M) { g_count[i] = 0; g_cur[i] = 0; }
    if (i < OUT_F * IN_F / 4) {
        float4 v = *reinterpret_cast<const float4*>(W + (size_t)i * 4);
        uint2 p = cvt4_f16(v);
        *reinterpret_cast<uint2*>(&g_Wh[i * 2]) = p;
    }
}

__device__ __forceinline__ int load_idx(const void* p, int i) {
    if (g_idx_is64) return (int)((const long long*)p)[i];
    return ((const int*)p)[i];
}

__global__ __launch_bounds__(256)
void hist_kernel(const void* __restrict__ dst, int E, int M) {
    int e = blockIdx.x * blockDim.x + threadIdx.x;
    if (e >= E) return;
    int d = load_idx(dst, e);
    if ((unsigned)d < (unsigned)M) atomicAdd(&g_count[d], 1);
}

__global__ __launch_bounds__(SCAN_BLK)
void scan1_kernel(int n) {
    __shared__ int sh[SCAN_BLK];
    int gid = blockIdx.x * SCAN_BLK + threadIdx.x;
    int v = (gid < n) ? g_count[gid] : 0;
    sh[threadIdx.x] = v;
    __syncthreads();
    #pragma unroll
    for (int s = 1; s < SCAN_BLK; s <<= 1) {
        int t = (threadIdx.x >= s) ? sh[threadIdx.x - s] : 0;
        __syncthreads();
        sh[threadIdx.x] += t;
        __syncthreads();
    }
    if (gid < n) g_off[gid] = sh[threadIdx.x] - v;
    if (threadIdx.x == SCAN_BLK - 1) g_blksum[blockIdx.x] = sh[threadIdx.x];
}

__global__ void scan2_kernel(int nblocks) {
    int run = 0;
    for (int i = 0; i < nblocks; i++) {
        int v = g_blksum[i];
        g_blksum[i] = run;
        run += v;
    }
}

__global__ __launch_bounds__(SCAN_BLK)
void scan3_kernel(int n) {
    int gid = blockIdx.x * SCAN_BLK + threadIdx.x;
    if (gid < n) g_off[gid] += g_blksum[blockIdx.x];
}

__global__ __launch_bounds__(256)
void fill_kernel(const void* __restrict__ src, const void* __restrict__ dst,
                 int E, int M) {
    int e = blockIdx.x * blockDim.x + threadIdx.x;
    if (e >= E) return;
    int s = load_idx(src, e);
    int d = load_idx(dst, e);
    if ((unsigned)s >= (unsigned)M || (unsigned)d >= (unsigned)M) return;
    int slot = g_off[d] + atomicAdd(&g_cur[d], 1);
    g_srcs[slot] = s;
}

// ---------------------------------------------------------------------------
// Pull-aggregate: HALF-WARP (16 lanes) per dst node, uint4 (16B) z loads.
// 2 nodes per warp, unroll-2 chains each -> 4 concurrent chains per warp.
// ---------------------------------------------------------------------------
__global__ __launch_bounds__(256)
void gather_kernel(const __half* __restrict__ z, float* __restrict__ out, int M) {
    int gtid = blockIdx.x * blockDim.x + threadIdx.x;
    int node = gtid >> 4;          // one 16-lane group per node
    int l16  = gtid & 15;
    if (node >= M) return;

    int beg = g_off[node];
    int cnt = g_count[node];

    float acc0[8] = {}, acc1[8] = {};

    int i = 0;
    for (; i + 2 <= cnt; i += 2) {
        int s0 = g_srcs[beg + i];
        int s1 = g_srcs[beg + i + 1];
        uint4 u0 = *reinterpret_cast<const uint4*>(z + (size_t)s0 * OUT_F + l16 * 8);
        uint4 u1 = *reinterpret_cast<const uint4*>(z + (size_t)s1 * OUT_F + l16 * 8);
        const unsigned* w0 = &u0.x;
        const unsigned* w1 = &u1.x;
        #pragma unroll
        for (int q = 0; q < 4; q++) {
            float2 a = __half22float2(*reinterpret_cast<const __half2*>(&w0[q]));
            float2 b = __half22float2(*reinterpret_cast<const __half2*>(&w1[q]));
            acc0[q * 2]     += a.x;
            acc0[q * 2 + 1] += a.y;
            acc1[q * 2]     += b.x;
            acc1[q * 2 + 1] += b.y;
        }
    }
    if (i < cnt) {
        int s0 = g_srcs[beg + i];
        uint4 u0 = *reinterpret_cast<const uint4*>(z + (size_t)s0 * OUT_F + l16 * 8);
        const unsigned* w0 = &u0.x;
        #pragma unroll
        for (int q = 0; q < 4; q++) {
            float2 a = __half22float2(*reinterpret_cast<const __half2*>(&w0[q]));
            acc0[q * 2]     += a.x;
            acc0[q * 2 + 1] += a.y;
        }
    }

    float inv = 1.0f / (float)(cnt > 0 ? cnt : 1);
    float* op = out + (size_t)node * OUT_F + l16 * 8;
    float4 r0, r1;
    r0.x = (acc0[0] + acc1[0]) * inv;  r0.y = (acc0[1] + acc1[1]) * inv;
    r0.z = (acc0[2] + acc1[2]) * inv;  r0.w = (acc0[3] + acc1[3]) * inv;
    r1.x = (acc0[4] + acc1[4]) * inv;  r1.y = (acc0[5] + acc1[5]) * inv;
    r1.z = (acc0[6] + acc1[6]) * inv;  r1.w = (acc0[7] + acc1[7]) * inv;
    *reinterpret_cast<float4*>(op)     = r0;
    *reinterpret_cast<float4*>(op + 4) = r1;
}

// ---------------------------------------------------------------------------
// Tensor-core GEMM with deep cp.async pipeline.
// A loaded as f32 via cp.async into a ring of 3 smem slots (2 chunks ahead),
// converted f32->fp16 per chunk (each thread converts what it copied).
// B (pre-converted fp16) cp.async'd into its own ring of 3; ldmatrix reads it
// directly. One committed group per chunk; wait_group 2 retires chunk c.
// ---------------------------------------------------------------------------
#define GBK 32
#define SPAD 40                        // fp16 tile row stride (elements)
#define FP16TILE (128 * SPAD * 2)      // 10240 B
#define RA_ROW 144                     // f32 A ring row stride (bytes) -> conflict-free LDS.128
#define RA_SLOT (128 * RA_ROW)         // 18432 B
#define RB_SLOT FP16TILE               // 10240 B
#define OFF_RA 0
#define OFF_RB (3 * RA_SLOT)                    // 55296
#define OFF_A16 (OFF_RB + 3 * RB_SLOT)          // 86016
#define SMEM_TOTAL_GEMM (OFF_A16 + 2 * FP16TILE) // 106496

__device__ __forceinline__ void ldsm_x4(unsigned r[4], unsigned saddr) {
    asm volatile("ldmatrix.sync.aligned.m8n8.x4.shared.b16 {%0,%1,%2,%3}, [%4];"
                 : "=r"(r[0]), "=r"(r[1]), "=r"(r[2]), "=r"(r[3]) : "r"(saddr));
}
__device__ __forceinline__ void mma_f16(float c[4], const unsigned a[4],
                                        const unsigned b[2]) {
    asm volatile("mma.sync.aligned.m16n8k16.row.col.f32.f16.f16.f32 "
                 "{%0,%1,%2,%3}, {%4,%5,%6,%7}, {%8,%9}, {%0,%1,%2,%3};"
                 : "+f"(c[0]), "+f"(c[1]), "+f"(c[2]), "+f"(c[3])
                 : "r"(a[0]), "r"(a[1]), "r"(a[2]), "r"(a[3]),
                   "r"(b[0]), "r"(b[1]));
}
__device__ __forceinline__ void cp16(unsigned sdst, const void* gsrc) {
    asm volatile("cp.async.cg.shared.global [%0], [%1], 16;"
                 :: "r"(sdst), "l"(gsrc));
}
__device__ __forceinline__ void cp16z(unsigned sdst, const void* gsrc, unsigned srcsz) {
    // src-size 0 -> zero-fill (OOB rows)
    asm volatile("cp.async.cg.shared.global [%0], [%1], 16, %2;"
                 :: "r"(sdst), "l"(gsrc), "r"(srcsz));
}

__global__ __launch_bounds__(256, 2)
void gemm_tc_kernel(const float* __restrict__ h, __half* __restrict__ z, int M) {
    extern __shared__ __align__(16) char dyn[];
    const unsigned uDyn = (unsigned)__cvta_generic_to_shared(dyn);

    const int tid  = threadIdx.x;
    const int warp = tid >> 5;
    const int lane = tid & 31;
    const int wm   = warp & 3;
    const int wn   = warp >> 2;
    const int rowBase = blockIdx.x * 128;

    // staging maps (thread t owns row t>>1, half cg = t&1 of 32-col chunk)
    const int ar = tid >> 1;
    const int cg = tid & 1;
    const unsigned asz = ((rowBase + ar) < M) ? 16u : 0u;
    const float* aptr = h + (size_t)(rowBase + ar) * IN_F + cg * 16;
    const unsigned raOff = (unsigned)(ar * RA_ROW + cg * 64);

    const int br = tid >> 1;
    const int bc = (tid & 1) * 8;
    const unsigned rbOff = (unsigned)(br * SPAD + bc * 2) * 2u;

    const int NCHUNK = IN_F / GBK;   // 8

    auto issue_chunk = [&](int c) {
        const unsigned ra = uDyn + OFF_RA + (c % 3) * RA_SLOT;
        const unsigned rb = uDyn + OFF_RB + (c % 3) * RB_SLOT;
        #pragma unroll
        for (int q = 0; q < 4; q++)
            cp16z(ra + raOff + q * 16, aptr + c * GBK + q * 4, asz);
        cp16(rb + rbOff,      &g_Wh[(size_t)br * (IN_F / 2) + c * (GBK / 2) + bc]);
        cp16(rb + rbOff + 16, &g_Wh[(size_t)br * (IN_F / 2) + c * (GBK / 2) + bc + 4]);
    };

    // prologue: chunks 0 and 1 in flight (one group each)
    issue_chunk(0);
    asm volatile("cp.async.commit_group;");
    issue_chunk(1);
    asm volatile("cp.async.commit_group;");

    float acc[2][8][4] = {};

    for (int c = 0; c < NCHUNK; c++) {
        // keep exactly one group per iteration (empty at tail) so wait_group 2
        // always retires chunk c's group
        if (c + 2 < NCHUNK) issue_chunk(c + 2);
        asm volatile("cp.async.commit_group;");
        asm volatile("cp.async.wait_group 2;");

        // convert own f32 rows -> fp16 tile (no cross-thread dep before sync)
        {
            const char* ra = dyn + OFF_RA + (c % 3) * RA_SLOT;
            char* a16 = dyn + OFF_A16 + (c & 1) * FP16TILE;
            #pragma unroll
            for (int q = 0; q < 4; q++) {
                float4 v = *reinterpret_cast<const float4*>(ra + raOff + q * 16);
                uint2 p = cvt4_f16(v);
                *reinterpret_cast<uint2*>(a16 + (ar * SPAD + cg * 16 + q * 4) * 2) = p;
            }
        }
        __syncthreads();   // fp16 A + ring B visible to all warps

        const unsigned sbA = uDyn + OFF_A16 + (c & 1) * FP16TILE;
        const unsigned sbB = uDyn + OFF_RB + (c % 3) * RB_SLOT;

        #pragma unroll
        for (int ks = 0; ks < GBK; ks += 16) {
            unsigned a[2][4];
            #pragma unroll
            for (int mt = 0; mt < 2; mt++) {
                int row = wm * 32 + mt * 16 + (lane & 15);
                int col = ks + ((lane >> 4) << 3);
                ldsm_x4(a[mt], sbA + (unsigned)(row * SPAD + col) * 2u);
            }
            #pragma unroll
            for (int np = 0; np < 4; np++) {
                int brow = wn * 64 + np * 16 + ((lane >> 4) << 3) + (lane & 7);
                int bcol = ks + (lane & 8);
                unsigned b4[4];
                ldsm_x4(b4, sbB + (unsigned)(brow * SPAD + bcol) * 2u);
                mma_f16(acc[0][np * 2],     a[0], b4);
                mma_f16(acc[1][np * 2],     a[1], b4);
                mma_f16(acc[0][np * 2 + 1], a[0], b4 + 2);
                mma_f16(acc[1][np * 2 + 1], a[1], b4 + 2);
            }
        }
        __syncthreads();   // all warps done with ring slot c%3 before it is re-filled
    }

    // ---- epilogue: store fp16 z ----
    const int g   = lane >> 2;
    const int tig = lane & 3;
    #pragma unroll
    for (int mt = 0; mt < 2; mt++) {
        #pragma unroll
        for (int nt = 0; nt < 8; nt++) {
            int row0 = rowBase + wm * 32 + mt * 16 + g;
            int col  = wn * 64 + nt * 8 + tig * 2;
            if (row0 < M) {
                __half2 v = __floats2half2_rn(acc[mt][nt][0], acc[mt][nt][1]);
                *reinterpret_cast<__half2*>(z + (size_t)row0 * OUT_F + col) = v;
            }
            int row1 = row0 + 8;
            if (row1 < M) {
                __half2 v = __floats2half2_rn(acc[mt][nt][2], acc[mt][nt][3]);
                *reinterpret_cast<__half2*>(z + (size_t)row1 * OUT_F + col) = v;
            }
        }
    }
}

// ---------------------------------------------------------------------------
extern "C" void kernel_launch(void* const* d_in, const int* in_sizes, int n_in,
                              void* d_out, int out_size) {
    const float* h   = (const float*)d_in[0];
    const float* W   = (const float*)d_in[1];
    const void*  src = d_in[2];
    const void*  dst = d_in[3];
    float* out = (float*)d_out;

    const int M = in_sizes[0] / IN_F;      // 100000
    const int E = in_sizes[2];             // 1600000

    __half* z;
    cudaGetSymbolAddress((void**)&z, g_z16);

    const int scan_blocks = (M + SCAN_BLK - 1) / SCAN_BLK;   // 98
    const int eb = (E + 255) / 256;                          // 6250

    cudaFuncSetAttribute(gemm_tc_kernel,
                         cudaFuncAttributeMaxDynamicSharedMemorySize, SMEM_TOTAL_GEMM);

    // prep feeds both branches
    prep_kernel<<<(M + 255) / 256, 256>>>((const unsigned long long*)src, E, W, M);

    // fork: CSR build on side stream, GEMM on main stream
    cudaEventRecord(g_evFork, 0);
    cudaStreamWaitEvent(g_s2, g_evFork, 0);

    gemm_tc_kernel<<<(M + 127) / 128, 256, SMEM_TOTAL_GEMM>>>(h, z, M);

    hist_kernel<<<eb, 256, 0, g_s2>>>(dst, E, M);
    scan1_kernel<<<scan_blocks, SCAN_BLK, 0, g_s2>>>(M);
    scan2_kernel<<<1, 1, 0, g_s2>>>(scan_blocks);
    scan3_kernel<<<scan_blocks, SCAN_BLK, 0, g_s2>>>(M);
    fill_kernel<<<eb, 256, 0, g_s2>>>(src, dst, E, M);

    // join: gather needs both z (main) and CSR (side)
    cudaEventRecord(g_evJoin, g_s2);
    cudaStreamWaitEvent(0, g_evJoin, 0);

    {
        long long threads = (long long)M * 16;   // 16 lanes per node
        int blocks = (int)((threads + 255) / 256);   // 6250
        gather_kernel<<<blocks, 256>>>(z, out, M);
    }
}

// round 12
// speedup vs baseline: 1.0705x; 1.0705x over previous
#include <cuda_runtime.h>
#include <cuda_fp16.h>
#include <cstdint>

// GCN layer: out = segment_mean( (h @ W^T)[src], dst )
//   h [100000,256] f32, W [128,256] f32, src/dst [1.6M] idx (dtype runtime-detected)
// fp16 single-pass HMMA GEMM (f32 accum) + fp16 z; CSR build overlapped with GEMM.
// This round: R10's proven GEMM + half-warp uint4 gather (single-variable change).

#define IN_F  256
#define OUT_F 128
#define MAX_NODES 100000
#define MAX_EDGES 1600000
#define SCAN_BLK  1024

__device__ __half   g_z16[(size_t)MAX_NODES * OUT_F];
__device__ int      g_count[MAX_NODES];
__device__ int      g_off[MAX_NODES];
__device__ int      g_cur[MAX_NODES];
__device__ int      g_srcs[MAX_EDGES];
__device__ int      g_blksum[(MAX_NODES + SCAN_BLK - 1) / SCAN_BLK + 1];
__device__ int      g_idx_is64;
__device__ unsigned g_Wh[OUT_F * IN_F / 2];   // W fp16 plane (packed f16x2)

static cudaStream_t g_s2;
static cudaEvent_t  g_evFork, g_evJoin;
static struct _StreamInit {
    _StreamInit() {
        cudaStreamCreateWithFlags(&g_s2, cudaStreamNonBlocking);
        cudaEventCreateWithFlags(&g_evFork, cudaEventDisableTiming);
        cudaEventCreateWithFlags(&g_evJoin, cudaEventDisableTiming);
    }
} g_streamInit;

// ---------------------------------------------------------------------------
__device__ __forceinline__ uint2 cvt4_f16(float4 v) {
    unsigned xy, zw;
    asm("cvt.rn.f16x2.f32 %0, %1, %2;" : "=r"(xy) : "f"(v.y), "f"(v.x));
    asm("cvt.rn.f16x2.f32 %0, %1, %2;" : "=r"(zw) : "f"(v.w), "f"(v.z));
    return make_uint2(xy, zw);
}

__global__ __launch_bounds__(256)
void prep_kernel(const unsigned long long* __restrict__ s64, int E,
                 const float* __restrict__ W, int M) {
    int i = blockIdx.x * blockDim.x + threadIdx.x;
    if (i == 0) {
        int n = E < 16 ? E : 16;
        int is64 = 1;
        for (int j = 0; j < n; j++)
            if ((s64[j] >> 32) != 0ull) { is64 = 0; break; }
        g_idx_is64 = is64;
    }
    if (i < M) { g_count[i] = 0; g_cur[i] = 0; }
    if (i < OUT_F * IN_F / 4) {
        float4 v = *reinterpret_cast<const float4*>(W + (size_t)i * 4);
        uint2 p = cvt4_f16(v);
        *reinterpret_cast<uint2*>(&g_Wh[i * 2]) = p;
    }
}

__device__ __forceinline__ int load_idx(const void* p, int i) {
    if (g_idx_is64) return (int)((const long long*)p)[i];
    return ((const int*)p)[i];
}

__global__ __launch_bounds__(256)
void hist_kernel(const void* __restrict__ dst, int E, int M) {
    int e = blockIdx.x * blockDim.x + threadIdx.x;
    if (e >= E) return;
    int d = load_idx(dst, e);
    if ((unsigned)d < (unsigned)M) atomicAdd(&g_count[d], 1);
}

__global__ __launch_bounds__(SCAN_BLK)
void scan1_kernel(int n) {
    __shared__ int sh[SCAN_BLK];
    int gid = blockIdx.x * SCAN_BLK + threadIdx.x;
    int v = (gid < n) ? g_count[gid] : 0;
    sh[threadIdx.x] = v;
    __syncthreads();
    #pragma unroll
    for (int s = 1; s < SCAN_BLK; s <<= 1) {
        int t = (threadIdx.x >= s) ? sh[threadIdx.x - s] : 0;
        __syncthreads();
        sh[threadIdx.x] += t;
        __syncthreads();
    }
    if (gid < n) g_off[gid] = sh[threadIdx.x] - v;
    if (threadIdx.x == SCAN_BLK - 1) g_blksum[blockIdx.x] = sh[threadIdx.x];
}

__global__ void scan2_kernel(int nblocks) {
    int run = 0;
    for (int i = 0; i < nblocks; i++) {
        int v = g_blksum[i];
        g_blksum[i] = run;
        run += v;
    }
}

__global__ __launch_bounds__(SCAN_BLK)
void scan3_kernel(int n) {
    int gid = blockIdx.x * SCAN_BLK + threadIdx.x;
    if (gid < n) g_off[gid] += g_blksum[blockIdx.x];
}

__global__ __launch_bounds__(256)
void fill_kernel(const void* __restrict__ src, const void* __restrict__ dst,
                 int E, int M) {
    int e = blockIdx.x * blockDim.x + threadIdx.x;
    if (e >= E) return;
    int s = load_idx(src, e);
    int d = load_idx(dst, e);
    if ((unsigned)s >= (unsigned)M || (unsigned)d >= (unsigned)M) return;
    int slot = g_off[d] + atomicAdd(&g_cur[d], 1);
    g_srcs[slot] = s;
}

// ---------------------------------------------------------------------------
// Pull-aggregate: HALF-WARP (16 lanes) per dst node, uint4 (16B) z loads.
// 2 nodes per warp, unroll-2 chains each -> 4 concurrent chains per warp.
// ---------------------------------------------------------------------------
__global__ __launch_bounds__(256)
void gather_kernel(const __half* __restrict__ z, float* __restrict__ out, int M) {
    int gtid = blockIdx.x * blockDim.x + threadIdx.x;
    int node = gtid >> 4;          // one 16-lane group per node
    int l16  = gtid & 15;
    if (node >= M) return;

    int beg = g_off[node];
    int cnt = g_count[node];

    float acc0[8] = {}, acc1[8] = {};

    int i = 0;
    for (; i + 2 <= cnt; i += 2) {
        int s0 = g_srcs[beg + i];
        int s1 = g_srcs[beg + i + 1];
        uint4 u0 = *reinterpret_cast<const uint4*>(z + (size_t)s0 * OUT_F + l16 * 8);
        uint4 u1 = *reinterpret_cast<const uint4*>(z + (size_t)s1 * OUT_F + l16 * 8);
        const unsigned* w0 = &u0.x;
        const unsigned* w1 = &u1.x;
        #pragma unroll
        for (int q = 0; q < 4; q++) {
            float2 a = __half22float2(*reinterpret_cast<const __half2*>(&w0[q]));
            float2 b = __half22float2(*reinterpret_cast<const __half2*>(&w1[q]));
            acc0[q * 2]     += a.x;
            acc0[q * 2 + 1] += a.y;
            acc1[q * 2]     += b.x;
            acc1[q * 2 + 1] += b.y;
        }
    }
    if (i < cnt) {
        int s0 = g_srcs[beg + i];
        uint4 u0 = *reinterpret_cast<const uint4*>(z + (size_t)s0 * OUT_F + l16 * 8);
        const unsigned* w0 = &u0.x;
        #pragma unroll
        for (int q = 0; q < 4; q++) {
            float2 a = __half22float2(*reinterpret_cast<const __half2*>(&w0[q]));
            acc0[q * 2]     += a.x;
            acc0[q * 2 + 1] += a.y;
        }
    }

    float inv = 1.0f / (float)(cnt > 0 ? cnt : 1);
    float* op = out + (size_t)node * OUT_F + l16 * 8;
    float4 r0, r1;
    r0.x = (acc0[0] + acc1[0]) * inv;  r0.y = (acc0[1] + acc1[1]) * inv;
    r0.z = (acc0[2] + acc1[2]) * inv;  r0.w = (acc0[3] + acc1[3]) * inv;
    r1.x = (acc0[4] + acc1[4]) * inv;  r1.y = (acc0[5] + acc1[5]) * inv;
    r1.z = (acc0[6] + acc1[6]) * inv;  r1.w = (acc0[7] + acc1[7]) * inv;
    *reinterpret_cast<float4*>(op)     = r0;
    *reinterpret_cast<float4*>(op + 4) = r1;
}

// ---------------------------------------------------------------------------
// Tensor-core GEMM, single-pass fp16 (f32 accum), double-buffered (R10-proven).
// Block 128x128, 8 warps (4x2), warp tile 32x64, K-chunk 32.
// B fragments via ldmatrix.x4 (one per nt-pair).
// ---------------------------------------------------------------------------
#define GBK 32
#define SPAD 40                       // padded fp16 row stride (elements)
#define PLANE (128 * SPAD * 2)        // 10240 bytes
#define STAGE (2 * PLANE)             // 20480 bytes (A + B)
#define OFF_A 0
#define OFF_B PLANE

__device__ __forceinline__ void ldsm_x4(unsigned r[4], unsigned saddr) {
    asm volatile("ldmatrix.sync.aligned.m8n8.x4.shared.b16 {%0,%1,%2,%3}, [%4];"
                 : "=r"(r[0]), "=r"(r[1]), "=r"(r[2]), "=r"(r[3]) : "r"(saddr));
}
__device__ __forceinline__ void mma_f16(float c[4], const unsigned a[4],
                                        const unsigned b[2]) {
    asm volatile("mma.sync.aligned.m16n8k16.row.col.f32.f16.f16.f32 "
                 "{%0,%1,%2,%3}, {%4,%5,%6,%7}, {%8,%9}, {%0,%1,%2,%3};"
                 : "+f"(c[0]), "+f"(c[1]), "+f"(c[2]), "+f"(c[3])
                 : "r"(a[0]), "r"(a[1]), "r"(a[2]), "r"(a[3]),
                   "r"(b[0]), "r"(b[1]));
}
__device__ __forceinline__ void cp16(unsigned sdst, const void* gsrc) {
    asm volatile("cp.async.cg.shared.global [%0], [%1], 16;"
                 :: "r"(sdst), "l"(gsrc));
}

__global__ __launch_bounds__(256, 2)
void gemm_tc_kernel(const float* __restrict__ h, __half* __restrict__ z, int M) {
    extern __shared__ __align__(16) char dyn[];
    const unsigned uDyn = (unsigned)__cvta_generic_to_shared(dyn);

    const int tid  = threadIdx.x;
    const int warp = tid >> 5;
    const int lane = tid & 31;
    const int wm   = warp & 3;
    const int wn   = warp >> 2;
    const int rowBase = blockIdx.x * 128;

    // A staging map
    const int ar = tid >> 1;
    const int ac = (tid & 1) * 16;
    const bool aval = (rowBase + ar) < M;
    const float* aptr = h + (size_t)(rowBase + ar) * IN_F + ac;

    // B staging map
    const int br = tid >> 1;
    const int bc = (tid & 1) * 8;
    const unsigned bSmemOff = (unsigned)(br * SPAD + bc * 2) * 2u;

    float acc[2][8][4] = {};
    float4 pf[4];

    // ---- prologue: stage chunk 0 into buffer 0 ----
    {
        const unsigned sb = uDyn;
        cp16(sb + OFF_B + bSmemOff,      &g_Wh[(size_t)br * (IN_F / 2) + bc]);
        cp16(sb + OFF_B + bSmemOff + 16, &g_Wh[(size_t)br * (IN_F / 2) + bc + 4]);
        asm volatile("cp.async.commit_group;");
        #pragma unroll
        for (int q = 0; q < 4; q++)
            pf[q] = aval ? *reinterpret_cast<const float4*>(aptr + q * 4)
                         : make_float4(0.f, 0.f, 0.f, 0.f);
        char* ab = dyn;
        #pragma unroll
        for (int q = 0; q < 4; q++) {
            uint2 p = cvt4_f16(pf[q]);
            int o = (ar * SPAD + ac + q * 4) * 2;
            *reinterpret_cast<uint2*>(ab + OFF_A + o) = p;
        }
        asm volatile("cp.async.wait_group 0;");
        __syncthreads();
    }

    const int NCHUNK = IN_F / GBK;   // 8
    for (int c = 0; c < NCHUNK; c++) {
        const int buf  = c & 1;
        const int nbuf = buf ^ 1;
        const unsigned sb  = uDyn + buf * STAGE;
        const unsigned snb = uDyn + nbuf * STAGE;
        const bool has_next = (c + 1 < NCHUNK);

        if (has_next) {
            const int k0n = (c + 1) * GBK;
            cp16(snb + OFF_B + bSmemOff,      &g_Wh[(size_t)br * (IN_F / 2) + k0n / 2 + bc]);
            cp16(snb + OFF_B + bSmemOff + 16, &g_Wh[(size_t)br * (IN_F / 2) + k0n / 2 + bc + 4]);
            asm volatile("cp.async.commit_group;");
            #pragma unroll
            for (int q = 0; q < 4; q++)
                pf[q] = aval ? *reinterpret_cast<const float4*>(aptr + k0n + q * 4)
                             : make_float4(0.f, 0.f, 0.f, 0.f);
        }

        // ---- MMAs on current buffer ----
        #pragma unroll
        for (int ks = 0; ks < GBK; ks += 16) {
            unsigned a[2][4];
            #pragma unroll
            for (int mt = 0; mt < 2; mt++) {
                int row = wm * 32 + mt * 16 + (lane & 15);
                int col = ks + ((lane >> 4) << 3);
                unsigned off = (unsigned)(row * SPAD + col) * 2u;
                ldsm_x4(a[mt], sb + OFF_A + off);
            }
            // B: one ldmatrix.x4 per nt-pair
            #pragma unroll
            for (int np = 0; np < 4; np++) {
                int brow = wn * 64 + np * 16 + ((lane >> 4) << 3) + (lane & 7);
                int bcol = ks + (lane & 8);
                unsigned off = (unsigned)(brow * SPAD + bcol) * 2u;
                unsigned b4[4];
                ldsm_x4(b4, sb + OFF_B + off);
                mma_f16(acc[0][np * 2],     a[0], b4);
                mma_f16(acc[1][np * 2],     a[1], b4);
                mma_f16(acc[0][np * 2 + 1], a[0], b4 + 2);
                mma_f16(acc[1][np * 2 + 1], a[1], b4 + 2);
            }
        }

        if (has_next) {
            char* ab = dyn + nbuf * STAGE;
            #pragma unroll
            for (int q = 0; q < 4; q++) {
                uint2 p = cvt4_f16(pf[q]);
                int o = (ar * SPAD + ac + q * 4) * 2;
                *reinterpret_cast<uint2*>(ab + OFF_A + o) = p;
            }
            asm volatile("cp.async.wait_group 0;");
        }
        __syncthreads();
    }

    // ---- epilogue: store fp16 z ----
    const int g   = lane >> 2;
    const int tig = lane & 3;
    #pragma unroll
    for (int mt = 0; mt < 2; mt++) {
        #pragma unroll
        for (int nt = 0; nt < 8; nt++) {
            int row0 = rowBase + wm * 32 + mt * 16 + g;
            int col  = wn * 64 + nt * 8 + tig * 2;
            if (row0 < M) {
                __half2 v = __floats2half2_rn(acc[mt][nt][0], acc[mt][nt][1]);
                *reinterpret_cast<__half2*>(z + (size_t)row0 * OUT_F + col) = v;
            }
            int row1 = row0 + 8;
            if (row1 < M) {
                __half2 v = __floats2half2_rn(acc[mt][nt][2], acc[mt][nt][3]);
                *reinterpret_cast<__half2*>(z + (size_t)row1 * OUT_F + col) = v;
            }
        }
    }
}

// ---------------------------------------------------------------------------
extern "C" void kernel_launch(void* const* d_in, const int* in_sizes, int n_in,
                              void* d_out, int out_size) {
    const float* h   = (const float*)d_in[0];
    const float* W   = (const float*)d_in[1];
    const void*  src = d_in[2];
    const void*  dst = d_in[3];
    float* out = (float*)d_out;

    const int M = in_sizes[0] / IN_F;      // 100000
    const int E = in_sizes[2];             // 1600000

    __half* z;
    cudaGetSymbolAddress((void**)&z, g_z16);

    const int scan_blocks = (M + SCAN_BLK - 1) / SCAN_BLK;   // 98
    const int eb = (E + 255) / 256;                          // 6250
    const int dynBytes = 2 * STAGE;                          // 40960

    cudaFuncSetAttribute(gemm_tc_kernel,
                         cudaFuncAttributeMaxDynamicSharedMemorySize, dynBytes);

    // prep feeds both branches
    prep_kernel<<<(M + 255) / 256, 256>>>((const unsigned long long*)src, E, W, M);

    // fork: CSR build on side stream, GEMM on main stream
    cudaEventRecord(g_evFork, 0);
    cudaStreamWaitEvent(g_s2, g_evFork, 0);

    gemm_tc_kernel<<<(M + 127) / 128, 256, dynBytes>>>(h, z, M);

    hist_kernel<<<eb, 256, 0, g_s2>>>(dst, E, M);
    scan1_kernel<<<scan_blocks, SCAN_BLK, 0, g_s2>>>(M);
    scan2_kernel<<<1, 1, 0, g_s2>>>(scan_blocks);
    scan3_kernel<<<scan_blocks, SCAN_BLK, 0, g_s2>>>(M);
    fill_kernel<<<eb, 256, 0, g_s2>>>(src, dst, E, M);

    // join: gather needs both z (main) and CSR (side)
    cudaEventRecord(g_evJoin, g_s2);
    cudaStreamWaitEvent(0, g_evJoin, 0);

    {
        long long threads = (long long)M * 16;   // 16 lanes per node
        int blocks = (int)((threads + 255) / 256);   // 6250
        gather_kernel<<<blocks, 256>>>(z, out, M);
    }
}